// round 12
// baseline (speedup 1.0000x reference)
#include <cuda_runtime.h>
#include <cuda_fp16.h>
#include <cstdint>
#include <cstddef>

#define Bn 16
#define Tn 2048
#define Dn 1024
#define Hn 512
#define Mn (Bn*Tn)      // 32768
#define Nn 3072
#define Kn 1024

// scratch (static __device__ arrays: allocation-free)
__device__ __half g_Wt[(size_t)Nn * Kn];  // [n'][k], n' = plane*1024 + z*512 + h  (fp16)
__device__ __half g_xh[(size_t)Mn * Kn];  // x in fp16
__device__ __half g_Uh[(size_t)Mn * Nn];  // U: plane0 = g raw, plane1 = sigmoid(f), plane2 = sigmoid(r)

// ------------------------------- helpers -------------------------------
__device__ __forceinline__ uint32_t smem_u32(const void* p) {
    uint32_t a;
    asm("{ .reg .u64 t; cvta.to.shared.u64 t, %1; cvt.u32.u64 %0, t; }" : "=r"(a) : "l"(p));
    return a;
}

#define SWZ(o) ((o) ^ (((o) >> 3) & 0x70))

__device__ __forceinline__ void cp_async16(uint32_t saddr, const void* gptr) {
    asm volatile("cp.async.cg.shared.global [%0], [%1], 16;" :: "r"(saddr), "l"(gptr) : "memory");
}
__device__ __forceinline__ void cp_commit() {
    asm volatile("cp.async.commit_group;" ::: "memory");
}
template<int N> __device__ __forceinline__ void cp_wait() {
    asm volatile("cp.async.wait_group %0;" :: "n"(N) : "memory");
}

#define LDSM4(r, addr) \
    asm volatile("ldmatrix.sync.aligned.m8n8.x4.shared.b16 {%0,%1,%2,%3}, [%4];" \
        : "=r"((r)[0]), "=r"((r)[1]), "=r"((r)[2]), "=r"((r)[3]) : "r"(addr))

#define MMA_F16(d, a, b) \
    asm volatile("mma.sync.aligned.m16n8k16.row.col.f32.f16.f16.f32 " \
        "{%0,%1,%2,%3}, {%4,%5,%6,%7}, {%8,%9}, {%0,%1,%2,%3};" \
        : "+f"((d)[0]), "+f"((d)[1]), "+f"((d)[2]), "+f"((d)[3]) \
        : "r"((a)[0]), "r"((a)[1]), "r"((a)[2]), "r"((a)[3]), "r"((b)[0]), "r"((b)[1]))

__device__ __forceinline__ float sigmoidf_(float v) {
    return __fdividef(1.f, 1.f + __expf(-v));
}

// ------------------------- Kernel 0a: x -> fp16 -------------------------
__global__ void __launch_bounds__(256) sru_xh(const float* __restrict__ x) {
    size_t i = (size_t)blockIdx.x * 256 + threadIdx.x;
    float4 v = ((const float4*)x)[i];
    __half2* o = (__half2*)g_xh + i * 2;
    o[0] = __floats2half2_rn(v.x, v.y);
    o[1] = __floats2half2_rn(v.z, v.w);
}

// ------------------------- Kernel 0b: W repack (tiled transpose, fp16) -------------------------
__global__ void __launch_bounds__(256) sru_wt(const float* __restrict__ W) {
    __shared__ float tile[32][33];
    const int tx = threadIdx.x, ty = threadIdx.y;   // 32 x 8
    const int zh0 = blockIdx.x * 32;
    const int d0  = blockIdx.y * 32;
    const int kk  = blockIdx.z;
    #pragma unroll
    for (int r = 0; r < 4; r++) {
        int d = d0 + ty + r * 8;
        int zh = zh0 + tx;
        tile[ty + r * 8][tx] = W[(size_t)d * 3072 + zh * 3 + kk];
    }
    __syncthreads();
    #pragma unroll
    for (int r = 0; r < 4; r++) {
        int zh = zh0 + ty + r * 8;
        int d  = d0 + tx;
        g_Wt[(size_t)(kk * 1024 + zh) * 1024 + d] = __float2half_rn(tile[tx][ty + r * 8]);
    }
}

// ------------------------- Kernel 1: fp16 mma.sync GEMM + fused gate activation -------------------------
#define BM 128
#define BN 128
#define BK 64
#define NCHUNK (Kn / BK)            // 16
#define ASZ (BM * 128)              // 16384 bytes
#define BSZ (BN * 128)              // 16384 bytes
#define STGB (ASZ + BSZ)            // 32768
#define STAGES 3
#define SMEM_TOTAL (STAGES * STGB)  // 98304

__global__ void __launch_bounds__(256, 2) sru_gemm(const float* __restrict__ bias) {
    extern __shared__ __align__(1024) char smem[];
    const uint32_t sb = smem_u32(smem);
    const int tid = threadIdx.x;
    const int lane = tid & 31;
    const int w = tid >> 5;                 // 0..7
    const int m0 = blockIdx.y * BM;
    const int n0 = blockIdx.x * BN;
    const int wm = (w & 3) * 32;            // 4 m-warps
    const int wn = (w >> 2) * 64;           // 2 n-warps

    const int rr  = tid >> 3;   // 0..31
    const int seg = tid & 7;    // 0..7
    const __half* aS = g_xh + (size_t)(m0 + rr) * Kn + seg * 8;
    const __half* bS = g_Wt + (size_t)(n0 + rr) * Kn + seg * 8;
    uint32_t aO[4], bO[4];
    #pragma unroll
    for (int j = 0; j < 4; j++) {
        uint32_t o = (uint32_t)(rr + 32 * j) * 128 + seg * 16;
        aO[j] = SWZ(o);
        bO[j] = ASZ + SWZ(o);
    }

    auto ldchunk = [&](int c, int s) {
        uint32_t st = sb + (uint32_t)s * STGB;
        const __half* ap = aS + c * BK;
        const __half* bp = bS + c * BK;
        #pragma unroll
        for (int j = 0; j < 4; j++) cp_async16(st + aO[j], ap + (size_t)(32 * j) * Kn);
        #pragma unroll
        for (int j = 0; j < 4; j++) cp_async16(st + bO[j], bp + (size_t)(32 * j) * Kn);
        cp_commit();
    };

    uint32_t aRow[2], aXor[2];
    #pragma unroll
    for (int mi = 0; mi < 2; mi++) {
        uint32_t r = wm + mi * 16 + ((lane & 8) ? 8 : 0) + (lane & 7);
        aRow[mi] = r * 128; aXor[mi] = (r & 7) << 4;
    }
    const uint32_t aHi = (lane & 16) ? 16 : 0;
    uint32_t bRow[4], bXor[4];
    #pragma unroll
    for (int p = 0; p < 4; p++) {
        uint32_t r = wn + p * 16 + ((lane & 16) ? 8 : 0) + (lane & 7);
        bRow[p] = ASZ + r * 128; bXor[p] = (r & 7) << 4;
    }
    const uint32_t bHi = (lane & 8) ? 16 : 0;

    float acc[2][8][4];
    #pragma unroll
    for (int mi = 0; mi < 2; mi++)
        #pragma unroll
        for (int nj = 0; nj < 8; nj++)
            #pragma unroll
            for (int q = 0; q < 4; q++) acc[mi][nj][q] = 0.f;

    ldchunk(0, 0);
    ldchunk(1, 1);

    for (int i = 0; i < NCHUNK; i++) {
        int s = i % 3;
        if (i + 2 < NCHUNK) ldchunk(i + 2, (i + 2) % 3);
        if (i < NCHUNK - 2)       cp_wait<2>();
        else if (i == NCHUNK - 2) cp_wait<1>();
        else                      cp_wait<0>();
        __syncthreads();

        uint32_t st = sb + (uint32_t)s * STGB;
        #pragma unroll
        for (int ks = 0; ks < 4; ks++) {
            uint32_t koff = ks * 32;
            uint32_t ar[2][4], br[4][4];
            #pragma unroll
            for (int mi = 0; mi < 2; mi++)
                LDSM4(ar[mi], st + aRow[mi] + ((koff + aHi) ^ aXor[mi]));
            #pragma unroll
            for (int p = 0; p < 4; p++)
                LDSM4(br[p], st + bRow[p] + ((koff + bHi) ^ bXor[p]));
            #pragma unroll
            for (int mi = 0; mi < 2; mi++)
                #pragma unroll
                for (int nj = 0; nj < 8; nj++)
                    MMA_F16(acc[mi][nj], ar[mi], &br[nj >> 1][(nj & 1) * 2]);
        }
        __syncthreads();
    }

    // fused epilogue: plane 0 (g) raw; planes 1,2 -> sigmoid(v + bias)
    const int plane = n0 >> 10;             // BN=128, planes 1024-aligned -> uniform per CTA
    const int rowb = m0 + wm + (lane >> 2);
    const int colb = n0 + wn + (lane & 3) * 2;
    if (plane == 0) {
        #pragma unroll
        for (int mi = 0; mi < 2; mi++)
            #pragma unroll
            for (int nj = 0; nj < 8; nj++) {
                size_t base = (size_t)(rowb + mi * 16) * Nn + colb + nj * 8;
                *(__half2*)(g_Uh + base) = __floats2half2_rn(acc[mi][nj][0], acc[mi][nj][1]);
                *(__half2*)(g_Uh + base + 8 * (size_t)Nn) = __floats2half2_rn(acc[mi][nj][2], acc[mi][nj][3]);
            }
    } else {
        const float* bp = bias + (size_t)(plane - 1) * 512;     // [z][plane-1][h]
        #pragma unroll
        for (int nj = 0; nj < 8; nj++) {
            int c  = colb + nj * 8;
            int cp = c & 1023;
            int zz = cp >> 9, hh = cp & 511;    // hh even -> hh+1 same z
            float b0 = bp[zz * 1024 + hh];
            float b1 = bp[zz * 1024 + hh + 1];
            #pragma unroll
            for (int mi = 0; mi < 2; mi++) {
                size_t base = (size_t)(rowb + mi * 16) * Nn + c;
                float s00 = sigmoidf_(acc[mi][nj][0] + b0);
                float s01 = sigmoidf_(acc[mi][nj][1] + b1);
                float s10 = sigmoidf_(acc[mi][nj][2] + b0);
                float s11 = sigmoidf_(acc[mi][nj][3] + b1);
                *(__half2*)(g_Uh + base) = __floats2half2_rn(s00, s01);
                *(__half2*)(g_Uh + base + 8 * (size_t)Nn) = __floats2half2_rn(s10, s11);
            }
        }
    }
}

// ------------------------- Kernel 2: SRU scan, 64 steps/tile, 4 ch/warp, pre-activated gates -------------------------
// 512 blocks x 256 threads (8 warps); block = one (b,z) x 32 channels; warp w owns channels 4w..4w+3.
// Lane l covers timesteps 2l, 2l+1: local affine compose, pair K-S scan over 4 chains, fix-up.
#define NT64 (Tn / 64)    // 32 tiles

__global__ void __launch_bounds__(256, 4) sru_scan(float* __restrict__ out) {
    __shared__ __half sbuf[3][64][34];  // g, f(sig), r(sig) tiles [t][ch], 17-word rows (odd -> bank-clean)
    __shared__ __half xbuf[64][34];
    __shared__ float  obuf[64][33];

    const int tid = threadIdx.x;
    const int lane = tid & 31;
    const int w = tid >> 5;             // 0..7
    const int bx = blockIdx.x;          // 512 blocks: hg(16) z(2) b(16)
    const int hg = bx & 15;
    const int z  = (bx >> 4) & 1;
    const int b  = bx >> 5;
    const int h0 = hg * 32;
    const int fwd = (z == 0);
    const int c0 = 4 * w;

    const size_t bT = (size_t)b * Tn;
    const int tL = tid >> 2, sgL = tid & 3;     // loader: row tL (0..63), 8-half seg sgL (0..3)

    uint4 ru[3], rx;
    auto load_tile = [&](int it) {
        long t0 = fwd ? (long)it * 64 : (long)(NT64 - 1 - it) * 64;
        #pragma unroll
        for (int p = 0; p < 3; p++)
            ru[p] = *(const uint4*)(g_Uh + (bT + t0 + tL) * Nn + (size_t)p * 1024 + z * 512 + h0 + sgL * 8);
        rx = *(const uint4*)(g_xh + (bT + t0 + tL) * Kn + z * 512 + h0 + sgL * 8);
    };

    load_tile(0);
    float carry[4] = {0.f, 0.f, 0.f, 0.f};
    const int row0 = fwd ? 2 * lane     : 63 - 2 * lane;
    const int row1 = fwd ? 2 * lane + 1 : 62 - 2 * lane;

    for (int it = 0; it < NT64; it++) {
        // stage regs -> smem
        #pragma unroll
        for (int p = 0; p < 3; p++) {
            uint32_t* d = (uint32_t*)&sbuf[p][tL][sgL * 8];
            d[0] = ru[p].x; d[1] = ru[p].y; d[2] = ru[p].z; d[3] = ru[p].w;
        }
        {
            uint32_t* d = (uint32_t*)&xbuf[tL][sgL * 8];
            d[0] = rx.x; d[1] = rx.y; d[2] = rx.z; d[3] = rx.w;
        }
        __syncthreads();
        if (it + 1 < NT64) load_tile(it + 1);   // prefetch overlaps compute

        // read 2 timesteps x 4 channels (gates pre-activated)
        float2 Ga01 = __half22float2(*(const __half2*)&sbuf[0][row0][c0]);
        float2 Ga23 = __half22float2(*(const __half2*)&sbuf[0][row0][c0 + 2]);
        float2 Fa01 = __half22float2(*(const __half2*)&sbuf[1][row0][c0]);
        float2 Fa23 = __half22float2(*(const __half2*)&sbuf[1][row0][c0 + 2]);
        float2 Ra01 = __half22float2(*(const __half2*)&sbuf[2][row0][c0]);
        float2 Ra23 = __half22float2(*(const __half2*)&sbuf[2][row0][c0 + 2]);
        float2 Xa01 = __half22float2(*(const __half2*)&xbuf[row0][c0]);
        float2 Xa23 = __half22float2(*(const __half2*)&xbuf[row0][c0 + 2]);
        float2 Gb01 = __half22float2(*(const __half2*)&sbuf[0][row1][c0]);
        float2 Gb23 = __half22float2(*(const __half2*)&sbuf[0][row1][c0 + 2]);
        float2 Fb01 = __half22float2(*(const __half2*)&sbuf[1][row1][c0]);
        float2 Fb23 = __half22float2(*(const __half2*)&sbuf[1][row1][c0 + 2]);
        float2 Rb01 = __half22float2(*(const __half2*)&sbuf[2][row1][c0]);
        float2 Rb23 = __half22float2(*(const __half2*)&sbuf[2][row1][c0 + 2]);
        float2 Xb01 = __half22float2(*(const __half2*)&xbuf[row1][c0]);
        float2 Xb23 = __half22float2(*(const __half2*)&xbuf[row1][c0 + 2]);

        float Ga[4] = {Ga01.x, Ga01.y, Ga23.x, Ga23.y};
        float aa[4] = {Fa01.x, Fa01.y, Fa23.x, Fa23.y};
        float Ra[4] = {Ra01.x, Ra01.y, Ra23.x, Ra23.y};
        float Xa[4] = {Xa01.x, Xa01.y, Xa23.x, Xa23.y};
        float Gb[4] = {Gb01.x, Gb01.y, Gb23.x, Gb23.y};
        float ab[4] = {Fb01.x, Fb01.y, Fb23.x, Fb23.y};
        float Rb[4] = {Rb01.x, Rb01.y, Rb23.x, Rb23.y};
        float Xb[4] = {Xb01.x, Xb01.y, Xb23.x, Xb23.y};

        float ba[4], bb[4], A[4], Bv[4];
        #pragma unroll
        for (int c = 0; c < 4; c++) {
            ba[c] = (1.f - aa[c]) * Ga[c];
            bb[c] = (1.f - ab[c]) * Gb[c];
            A[c]  = ab[c] * aa[c];                 // pair compose
            Bv[c] = fmaf(ab[c], ba[c], bb[c]);
        }

        // Kogge-Stone inclusive scan over pairs, 4 channels interleaved
        #pragma unroll
        for (int d = 1; d < 32; d <<= 1) {
            float Ap[4], Bp[4];
            #pragma unroll
            for (int c = 0; c < 4; c++) {
                Ap[c] = __shfl_up_sync(0xFFFFFFFFu, A[c], d);
                Bp[c] = __shfl_up_sync(0xFFFFFFFFu, Bv[c], d);
            }
            if (lane >= d) {
                #pragma unroll
                for (int c = 0; c < 4; c++) {
                    Bv[c] = fmaf(A[c], Bp[c], Bv[c]);
                    A[c] *= Ap[c];
                }
            }
        }

        float ca[4], cb[4];
        #pragma unroll
        for (int c = 0; c < 4; c++) {
            float Ae = __shfl_up_sync(0xFFFFFFFFu, A[c], 1);
            float Be = __shfl_up_sync(0xFFFFFFFFu, Bv[c], 1);
            if (lane == 0) { Ae = 1.f; Be = 0.f; }
            float cin = fmaf(Ae, carry[c], Be);
            ca[c] = fmaf(aa[c], cin, ba[c]);
            cb[c] = fmaf(ab[c], ca[c], bb[c]);
            float At = __shfl_sync(0xFFFFFFFFu, A[c], 31);
            float Bt = __shfl_sync(0xFFFFFFFFu, Bv[c], 31);
            carry[c] = fmaf(At, carry[c], Bt);
        }

        #pragma unroll
        for (int c = 0; c < 4; c++) {
            float tha = 1.f - 2.f * __fdividef(1.f, 1.f + __expf(2.f * ca[c]));
            float thb = 1.f - 2.f * __fdividef(1.f, 1.f + __expf(2.f * cb[c]));
            obuf[row0][c0 + c] = fmaf(Ra[c], tha - Xa[c], Xa[c]);
            obuf[row1][c0 + c] = fmaf(Rb[c], thb - Xb[c], Xb[c]);
        }
        __syncthreads();

        // coalesced store: 512 float4 over 256 threads (2 each); no trailing sync needed
        {
            long t0 = fwd ? (long)it * 64 : (long)(NT64 - 1 - it) * 64;
            #pragma unroll
            for (int j = 0; j < 2; j++) {
                int idx = tid + 256 * j;
                int t = idx >> 3, sg = idx & 7;
                float4 v = make_float4(obuf[t][sg * 4], obuf[t][sg * 4 + 1],
                                       obuf[t][sg * 4 + 2], obuf[t][sg * 4 + 3]);
                *(float4*)(out + (bT + t0 + t) * Dn + z * 512 + h0 + sg * 4) = v;
            }
        }
    }

    // c_last: (B, 1, 2H) appended after out
    if (lane == 0) {
        float4 v = make_float4(carry[0], carry[1], carry[2], carry[3]);
        *(float4*)(out + (size_t)Bn * Tn * Dn + (size_t)b * 1024 + z * 512 + h0 + c0) = v;
    }
}

// ------------------------------- launch -------------------------------
extern "C" void kernel_launch(void* const* d_in, const int* in_sizes, int n_in,
                              void* d_out, int out_size) {
    const float* x    = (const float*)d_in[0];
    const float* W    = (const float*)d_in[1];
    const float* bias = (const float*)d_in[2];
    float* out = (float*)d_out;
    (void)in_sizes; (void)n_in; (void)out_size;

    cudaFuncSetAttribute(sru_gemm, cudaFuncAttributeMaxDynamicSharedMemorySize, SMEM_TOTAL);

    sru_xh  <<<(Mn * (Kn / 4)) / 256, 256>>>(x);
    sru_wt  <<<dim3(32, 32, 3), dim3(32, 8)>>>(W);
    sru_gemm<<<dim3(Nn / BN, Mn / BM), 256, SMEM_TOTAL>>>(bias);
    sru_scan<<<512, 256>>>(out);
}

// round 13
// speedup vs baseline: 1.0281x; 1.0281x over previous
#include <cuda_runtime.h>
#include <cuda_fp16.h>
#include <cstdint>
#include <cstddef>

#define Bn 16
#define Tn 2048
#define Dn 1024
#define Hn 512
#define Mn (Bn*Tn)      // 32768
#define Nn 3072
#define Kn 1024

// scratch (static __device__ arrays: allocation-free)
__device__ __half g_Wt[(size_t)Nn * Kn];  // [n'][k], n' = plane*1024 + z*512 + h  (fp16)
__device__ __half g_xh[(size_t)Mn * Kn];  // x in fp16
__device__ __half g_Uh[(size_t)Mn * Nn];  // U in fp16: [m][n'], m = b*T + t

// ------------------------------- helpers -------------------------------
__device__ __forceinline__ uint32_t smem_u32(const void* p) {
    uint32_t a;
    asm("{ .reg .u64 t; cvta.to.shared.u64 t, %1; cvt.u32.u64 %0, t; }" : "=r"(a) : "l"(p));
    return a;
}

#define SWZ(o) ((o) ^ (((o) >> 3) & 0x70))

__device__ __forceinline__ void cp_async16(uint32_t saddr, const void* gptr) {
    asm volatile("cp.async.cg.shared.global [%0], [%1], 16;" :: "r"(saddr), "l"(gptr) : "memory");
}
__device__ __forceinline__ void cp_commit() {
    asm volatile("cp.async.commit_group;" ::: "memory");
}
template<int N> __device__ __forceinline__ void cp_wait() {
    asm volatile("cp.async.wait_group %0;" :: "n"(N) : "memory");
}

#define LDSM4(r, addr) \
    asm volatile("ldmatrix.sync.aligned.m8n8.x4.shared.b16 {%0,%1,%2,%3}, [%4];" \
        : "=r"((r)[0]), "=r"((r)[1]), "=r"((r)[2]), "=r"((r)[3]) : "r"(addr))

#define MMA_F16(d, a, b) \
    asm volatile("mma.sync.aligned.m16n8k16.row.col.f32.f16.f16.f32 " \
        "{%0,%1,%2,%3}, {%4,%5,%6,%7}, {%8,%9}, {%0,%1,%2,%3};" \
        : "+f"((d)[0]), "+f"((d)[1]), "+f"((d)[2]), "+f"((d)[3]) \
        : "r"((a)[0]), "r"((a)[1]), "r"((a)[2]), "r"((a)[3]), "r"((b)[0]), "r"((b)[1]))

// ------------------------- Kernel 0a: x -> fp16 -------------------------
__global__ void __launch_bounds__(256) sru_xh(const float* __restrict__ x) {
    size_t i = (size_t)blockIdx.x * 256 + threadIdx.x;
    float4 v = ((const float4*)x)[i];
    __half2* o = (__half2*)g_xh + i * 2;
    o[0] = __floats2half2_rn(v.x, v.y);
    o[1] = __floats2half2_rn(v.z, v.w);
}

// ------------------------- Kernel 0b: W repack (tiled transpose, fp16) -------------------------
__global__ void __launch_bounds__(256) sru_wt(const float* __restrict__ W) {
    __shared__ float tile[32][33];
    const int tx = threadIdx.x, ty = threadIdx.y;   // 32 x 8
    const int zh0 = blockIdx.x * 32;
    const int d0  = blockIdx.y * 32;
    const int kk  = blockIdx.z;
    #pragma unroll
    for (int r = 0; r < 4; r++) {
        int d = d0 + ty + r * 8;
        int zh = zh0 + tx;
        tile[ty + r * 8][tx] = W[(size_t)d * 3072 + zh * 3 + kk];
    }
    __syncthreads();
    #pragma unroll
    for (int r = 0; r < 4; r++) {
        int zh = zh0 + ty + r * 8;
        int d  = d0 + tx;
        g_Wt[(size_t)(kk * 1024 + zh) * 1024 + d] = __float2half_rn(tile[tx][ty + r * 8]);
    }
}

// ------------------------- Kernel 1: fp16 mma.sync GEMM, 128x128 tiles, 2 CTAs/SM, 1 barrier/chunk -------------------------
#define BM 128
#define BN 128
#define BK 64
#define NCHUNK (Kn / BK)            // 16
#define ASZ (BM * 128)              // 16384 bytes
#define BSZ (BN * 128)              // 16384 bytes
#define STGB (ASZ + BSZ)            // 32768
#define STAGES 3
#define SMEM_TOTAL (STAGES * STGB)  // 98304

__global__ void __launch_bounds__(256, 2) sru_gemm() {
    extern __shared__ __align__(1024) char smem[];
    const uint32_t sb = smem_u32(smem);
    const int tid = threadIdx.x;
    const int lane = tid & 31;
    const int w = tid >> 5;                 // 0..7
    const int m0 = blockIdx.y * BM;
    const int n0 = blockIdx.x * BN;
    const int wm = (w & 3) * 32;            // 4 m-warps
    const int wn = (w >> 2) * 64;           // 2 n-warps

    const int rr  = tid >> 3;   // 0..31
    const int seg = tid & 7;    // 0..7
    const __half* aS = g_xh + (size_t)(m0 + rr) * Kn + seg * 8;
    const __half* bS = g_Wt + (size_t)(n0 + rr) * Kn + seg * 8;
    uint32_t aO[4], bO[4];
    #pragma unroll
    for (int j = 0; j < 4; j++) {
        uint32_t o = (uint32_t)(rr + 32 * j) * 128 + seg * 16;
        aO[j] = SWZ(o);
        bO[j] = ASZ + SWZ(o);
    }

    auto ldchunk = [&](int c, int s) {
        uint32_t st = sb + (uint32_t)s * STGB;
        const __half* ap = aS + c * BK;
        const __half* bp = bS + c * BK;
        #pragma unroll
        for (int j = 0; j < 4; j++) cp_async16(st + aO[j], ap + (size_t)(32 * j) * Kn);
        #pragma unroll
        for (int j = 0; j < 4; j++) cp_async16(st + bO[j], bp + (size_t)(32 * j) * Kn);
        cp_commit();
    };

    uint32_t aRow[2], aXor[2];
    #pragma unroll
    for (int mi = 0; mi < 2; mi++) {
        uint32_t r = wm + mi * 16 + ((lane & 8) ? 8 : 0) + (lane & 7);
        aRow[mi] = r * 128; aXor[mi] = (r & 7) << 4;
    }
    const uint32_t aHi = (lane & 16) ? 16 : 0;
    uint32_t bRow[4], bXor[4];
    #pragma unroll
    for (int p = 0; p < 4; p++) {
        uint32_t r = wn + p * 16 + ((lane & 16) ? 8 : 0) + (lane & 7);
        bRow[p] = ASZ + r * 128; bXor[p] = (r & 7) << 4;
    }
    const uint32_t bHi = (lane & 8) ? 16 : 0;

    float acc[2][8][4];
    #pragma unroll
    for (int mi = 0; mi < 2; mi++)
        #pragma unroll
        for (int nj = 0; nj < 8; nj++)
            #pragma unroll
            for (int q = 0; q < 4; q++) acc[mi][nj][q] = 0.f;

    // prologue: chunks 0,1 into stages 0,1
    ldchunk(0, 0);
    ldchunk(1, 1);

    // Single barrier per chunk:
    //   cp_wait<1>  -> this thread's group i complete (one newer group i+1 may be in flight)
    //   syncthreads -> everyone's group-i data visible; all warps done READING chunk i-1's stage
    //   ldchunk(i+2) into stage (i+2)%3 = (i-1)%3 -- safe, its readers all passed the barrier
    //   compute chunk i from stage i%3
    for (int i = 0; i < NCHUNK; i++) {
        if (i < NCHUNK - 1) cp_wait<1>();
        else                cp_wait<0>();
        __syncthreads();
        if (i + 2 < NCHUNK) ldchunk(i + 2, (i + 2) % 3);

        uint32_t st = sb + (uint32_t)(i % 3) * STGB;
        #pragma unroll
        for (int ks = 0; ks < 4; ks++) {
            uint32_t koff = ks * 32;
            uint32_t ar[2][4], br[4][4];
            #pragma unroll
            for (int mi = 0; mi < 2; mi++)
                LDSM4(ar[mi], st + aRow[mi] + ((koff + aHi) ^ aXor[mi]));
            #pragma unroll
            for (int p = 0; p < 4; p++)
                LDSM4(br[p], st + bRow[p] + ((koff + bHi) ^ bXor[p]));
            #pragma unroll
            for (int mi = 0; mi < 2; mi++)
                #pragma unroll
                for (int nj = 0; nj < 8; nj++)
                    MMA_F16(acc[mi][nj], ar[mi], &br[nj >> 1][(nj & 1) * 2]);
        }
        // no trailing sync: next iteration's barrier gates the stage reuse
    }

    // fp16 epilogue
    const int rowb = m0 + wm + (lane >> 2);
    const int colb = n0 + wn + (lane & 3) * 2;
    #pragma unroll
    for (int mi = 0; mi < 2; mi++)
        #pragma unroll
        for (int nj = 0; nj < 8; nj++) {
            size_t base = (size_t)(rowb + mi * 16) * Nn + colb + nj * 8;
            *(__half2*)(g_Uh + base) = __floats2half2_rn(acc[mi][nj][0], acc[mi][nj][1]);
            *(__half2*)(g_Uh + base + 8 * (size_t)Nn) = __floats2half2_rn(acc[mi][nj][2], acc[mi][nj][3]);
        }
}

// ------------------------- Kernel 2: SRU scan, 64 steps/tile, 4 ch/warp (ILP-4) -------------------------
#define NT64 (Tn / 64)    // 32 tiles

__global__ void __launch_bounds__(512, 2) sru_scan(const float* __restrict__ bias,
                                                   float* __restrict__ out) {
    __shared__ __half sbuf[3][64][66];  // g,f,r tiles [t][ch], 33-word rows (odd -> bank-clean)
    __shared__ __half xbuf[64][66];
    __shared__ float  obuf[64][65];

    const int tid = threadIdx.x;
    const int lane = tid & 31;
    const int w = tid >> 5;             // 0..15
    const int bx = blockIdx.x;          // 256 blocks: hg(8) z(2) b(16)
    const int hg = bx & 7;
    const int z  = (bx >> 3) & 1;
    const int b  = bx >> 4;
    const int h0 = hg * 64;
    const int fwd = (z == 0);
    const int c0 = 4 * w;

    float bf[4], br[4];
    #pragma unroll
    for (int c = 0; c < 4; c++) {
        bf[c] = bias[z * 1024 + h0 + c0 + c];
        br[c] = bias[z * 1024 + 512 + h0 + c0 + c];
    }

    const size_t bT = (size_t)b * Tn;
    const int tL = tid >> 3, sgL = tid & 7;     // loader role: row tL, 8-half seg sgL

    uint4 ru[3], rx;
    auto load_tile = [&](int it) {
        long t0 = fwd ? (long)it * 64 : (long)(NT64 - 1 - it) * 64;
        #pragma unroll
        for (int p = 0; p < 3; p++)
            ru[p] = *(const uint4*)(g_Uh + (bT + t0 + tL) * Nn + (size_t)p * 1024 + z * 512 + h0 + sgL * 8);
        rx = *(const uint4*)(g_xh + (bT + t0 + tL) * Kn + z * 512 + h0 + sgL * 8);
    };

    load_tile(0);
    float carry[4] = {0.f, 0.f, 0.f, 0.f};
    const int row0 = fwd ? 2 * lane     : 63 - 2 * lane;
    const int row1 = fwd ? 2 * lane + 1 : 62 - 2 * lane;

    for (int it = 0; it < NT64; it++) {
        // stage regs -> smem
        #pragma unroll
        for (int p = 0; p < 3; p++) {
            uint32_t* d = (uint32_t*)&sbuf[p][tL][sgL * 8];
            d[0] = ru[p].x; d[1] = ru[p].y; d[2] = ru[p].z; d[3] = ru[p].w;
        }
        {
            uint32_t* d = (uint32_t*)&xbuf[tL][sgL * 8];
            d[0] = rx.x; d[1] = rx.y; d[2] = rx.z; d[3] = rx.w;
        }
        __syncthreads();
        if (it + 1 < NT64) load_tile(it + 1);   // prefetch overlaps compute

        // read 2 timesteps x 4 channels
        float2 Ga01 = __half22float2(*(const __half2*)&sbuf[0][row0][c0]);
        float2 Ga23 = __half22float2(*(const __half2*)&sbuf[0][row0][c0 + 2]);
        float2 Fa01 = __half22float2(*(const __half2*)&sbuf[1][row0][c0]);
        float2 Fa23 = __half22float2(*(const __half2*)&sbuf[1][row0][c0 + 2]);
        float2 Ra01 = __half22float2(*(const __half2*)&sbuf[2][row0][c0]);
        float2 Ra23 = __half22float2(*(const __half2*)&sbuf[2][row0][c0 + 2]);
        float2 Xa01 = __half22float2(*(const __half2*)&xbuf[row0][c0]);
        float2 Xa23 = __half22float2(*(const __half2*)&xbuf[row0][c0 + 2]);
        float2 Gb01 = __half22float2(*(const __half2*)&sbuf[0][row1][c0]);
        float2 Gb23 = __half22float2(*(const __half2*)&sbuf[0][row1][c0 + 2]);
        float2 Fb01 = __half22float2(*(const __half2*)&sbuf[1][row1][c0]);
        float2 Fb23 = __half22float2(*(const __half2*)&sbuf[1][row1][c0 + 2]);
        float2 Rb01 = __half22float2(*(const __half2*)&sbuf[2][row1][c0]);
        float2 Rb23 = __half22float2(*(const __half2*)&sbuf[2][row1][c0 + 2]);
        float2 Xb01 = __half22float2(*(const __half2*)&xbuf[row1][c0]);
        float2 Xb23 = __half22float2(*(const __half2*)&xbuf[row1][c0 + 2]);

        float Ga[4] = {Ga01.x, Ga01.y, Ga23.x, Ga23.y};
        float Fa[4] = {Fa01.x, Fa01.y, Fa23.x, Fa23.y};
        float Ra[4] = {Ra01.x, Ra01.y, Ra23.x, Ra23.y};
        float Xa[4] = {Xa01.x, Xa01.y, Xa23.x, Xa23.y};
        float Gb[4] = {Gb01.x, Gb01.y, Gb23.x, Gb23.y};
        float Fb[4] = {Fb01.x, Fb01.y, Fb23.x, Fb23.y};
        float Rb[4] = {Rb01.x, Rb01.y, Rb23.x, Rb23.y};
        float Xb[4] = {Xb01.x, Xb01.y, Xb23.x, Xb23.y};

        float aa[4], ab[4], ba[4], bb[4], A[4], Bv[4];
        #pragma unroll
        for (int c = 0; c < 4; c++) {
            aa[c] = __fdividef(1.f, 1.f + __expf(-(Fa[c] + bf[c])));   // step0 coeff
            ab[c] = __fdividef(1.f, 1.f + __expf(-(Fb[c] + bf[c])));   // step1 coeff
            ba[c] = (1.f - aa[c]) * Ga[c];
            bb[c] = (1.f - ab[c]) * Gb[c];
            A[c]  = ab[c] * aa[c];                 // pair compose
            Bv[c] = fmaf(ab[c], ba[c], bb[c]);
        }

        // Kogge-Stone inclusive scan over pairs, 4 channels interleaved
        #pragma unroll
        for (int d = 1; d < 32; d <<= 1) {
            float Ap[4], Bp[4];
            #pragma unroll
            for (int c = 0; c < 4; c++) {
                Ap[c] = __shfl_up_sync(0xFFFFFFFFu, A[c], d);
                Bp[c] = __shfl_up_sync(0xFFFFFFFFu, Bv[c], d);
            }
            if (lane >= d) {
                #pragma unroll
                for (int c = 0; c < 4; c++) {
                    Bv[c] = fmaf(A[c], Bp[c], Bv[c]);
                    A[c] *= Ap[c];
                }
            }
        }

        float ca[4], cb[4];
        #pragma unroll
        for (int c = 0; c < 4; c++) {
            float Ae = __shfl_up_sync(0xFFFFFFFFu, A[c], 1);
            float Be = __shfl_up_sync(0xFFFFFFFFu, Bv[c], 1);
            if (lane == 0) { Ae = 1.f; Be = 0.f; }
            float cin = fmaf(Ae, carry[c], Be);
            ca[c] = fmaf(aa[c], cin, ba[c]);
            cb[c] = fmaf(ab[c], ca[c], bb[c]);
            float At = __shfl_sync(0xFFFFFFFFu, A[c], 31);
            float Bt = __shfl_sync(0xFFFFFFFFu, Bv[c], 31);
            carry[c] = fmaf(At, carry[c], Bt);
        }

        #pragma unroll
        for (int c = 0; c < 4; c++) {
            float rva = __fdividef(1.f, 1.f + __expf(-(Ra[c] + br[c])));
            float rvb = __fdividef(1.f, 1.f + __expf(-(Rb[c] + br[c])));
            float tha = 1.f - 2.f * __fdividef(1.f, 1.f + __expf(2.f * ca[c]));
            float thb = 1.f - 2.f * __fdividef(1.f, 1.f + __expf(2.f * cb[c]));
            obuf[row0][c0 + c] = fmaf(rva, tha - Xa[c], Xa[c]);
            obuf[row1][c0 + c] = fmaf(rvb, thb - Xb[c], Xb[c]);
        }
        __syncthreads();

        // coalesced store: 1024 float4 over 512 threads (2 each); no trailing sync needed
        {
            long t0 = fwd ? (long)it * 64 : (long)(NT64 - 1 - it) * 64;
            #pragma unroll
            for (int j = 0; j < 2; j++) {
                int idx = tid + 512 * j;
                int t = idx >> 4, sg = idx & 15;
                float4 v = make_float4(obuf[t][sg * 4], obuf[t][sg * 4 + 1],
                                       obuf[t][sg * 4 + 2], obuf[t][sg * 4 + 3]);
                *(float4*)(out + (bT + t0 + t) * Dn + z * 512 + h0 + sg * 4) = v;
            }
        }
    }

    // c_last: (B, 1, 2H) appended after out
    if (lane == 0) {
        float4 v = make_float4(carry[0], carry[1], carry[2], carry[3]);
        *(float4*)(out + (size_t)Bn * Tn * Dn + (size_t)b * 1024 + z * 512 + h0 + c0) = v;
    }
}

// ------------------------------- launch -------------------------------
extern "C" void kernel_launch(void* const* d_in, const int* in_sizes, int n_in,
                              void* d_out, int out_size) {
    const float* x    = (const float*)d_in[0];
    const float* W    = (const float*)d_in[1];
    const float* bias = (const float*)d_in[2];
    float* out = (float*)d_out;
    (void)in_sizes; (void)n_in; (void)out_size;

    cudaFuncSetAttribute(sru_gemm, cudaFuncAttributeMaxDynamicSharedMemorySize, SMEM_TOTAL);

    sru_xh  <<<(Mn * (Kn / 4)) / 256, 256>>>(x);
    sru_wt  <<<dim3(32, 32, 3), dim3(32, 8)>>>(W);
    sru_gemm<<<dim3(Nn / BN, Mn / BM), 256, SMEM_TOTAL>>>();
    sru_scan<<<256, 512>>>(bias, out);
}